// round 11
// baseline (speedup 1.0000x reference)
#include <cuda_runtime.h>
#include <math_constants.h>

// Morphological opening: dilate3x3(erode3x3(x)), flat SE, geodesic SAME padding.
// x: (16,3,1024,1024) f32 -> 48 planes of 1024x1024.
//
// Converged design (R7 winner + micro-cleanups):
//   - warp owns 128 loaded cols (lane l = cols 4l..4l+3 as float4), 124 valid
//     output cols; tiles stride 124 (9 x-tiles, last anchored at 896)
//   - horizontal min3/max3 via warp shuffles; interior edge lanes masked at store
//   - vertical pad via clamp-to-edge row replication (identity for min windows);
//     dilation -inf pad handled on image top/bottom tiles only (guarded path)
//   - interior tiles (94%) run a pointer-incremented, guard-free loop
//   - 3-deep row prefetch in registers, 3/2-deep vertical rings, unroll 6
//   - TH=32 -> 6912 blocks of 64 thr at 16 blk/SM = 2.92 waves (tail ~3%)
//   - measured at the practical HBM ceiling: ~401MB total DRAM traffic (floor),
//     ~5.9 TB/s sustained

#define TH      32
#define IMG_W   1024
#define IMG_H   1024
#define PLANES  48
#define TILES_X 9
#define TILE_STRIDE 124
#define TILES_Y (IMG_H / TH)    // 32

__device__ __forceinline__ float min3f(float a, float b, float c) {
    return fminf(a, fminf(b, c));
}
__device__ __forceinline__ float max3f(float a, float b, float c) {
    return fmaxf(a, fmaxf(b, c));
}

__global__ void __launch_bounds__(64, 16)
morph_open_kernel(const float* __restrict__ in, float* __restrict__ out) {
    const unsigned FULL = 0xffffffffu;
    const float INF  = CUDART_INF_F;
    const float NINF = -CUDART_INF_F;

    const int warp_g = blockIdx.x * 2 + (threadIdx.x >> 5);
    const int lane   = threadIdx.x & 31;

    const int tx = warp_g % TILES_X;
    const int ty = (warp_g / TILES_X) % TILES_Y;
    const int p  = warp_g / (TILES_X * TILES_Y);   // grid is exact; p < PLANES

    const float* __restrict__ base  = in  + (size_t)p * (IMG_W * IMG_H);
    float*       __restrict__ obase = out + (size_t)p * (IMG_W * IMG_H);

    // tile anchors: 0,124,...,868, then 896 (last tile right-aligned)
    const int x0 = (tx == TILES_X - 1) ? (IMG_W - 128) : tx * TILE_STRIDE;
    const int y0 = ty * TH;
    const int cbase = x0 + 4 * lane;
    const bool leftEdge  = (tx == 0);
    const bool rightEdge = (tx == TILES_X - 1);
    const bool isL = (lane == 0);
    const bool isR = (lane == 31);
    const bool storeFull = (!isL || leftEdge) && (!isR || rightEdge);

    // ---- horizontal min3 of one input row (shuffle-only)
    auto hminrow = [&](const float4& x, float4& h) {
        float xl = __shfl_up_sync(FULL, x.w, 1);
        if (isL) xl = INF;
        float xr = __shfl_down_sync(FULL, x.x, 1);
        if (isR) xr = INF;
        h.x = min3f(xl,  x.x, x.y);
        h.y = min3f(x.x, x.y, x.z);
        h.z = min3f(x.y, x.z, x.w);
        h.w = min3f(x.z, x.w, xr);
    };

    // ---- horizontal max3 of an erosion row (shuffle-only)
    auto hmaxrow = [&](const float4& e, float4& g) {
        float el = __shfl_up_sync(FULL, e.w, 1);
        if (isL) el = NINF;
        float er = __shfl_down_sync(FULL, e.x, 1);
        if (isR) er = NINF;
        g.x = max3f(el,  e.x, e.y);
        g.y = max3f(e.x, e.y, e.z);
        g.z = max3f(e.y, e.z, e.w);
        g.w = max3f(e.z, e.w, er);
    };

    // ---- shared epilogue: vertical mins, guard, store, ring rotation
    //      (templated on guard need; inlined into both paths)
    auto store_out = [&](const float4& o, float* orow) {
        if (storeFull) {
            __stcs(reinterpret_cast<float4*>(orow), o);
        } else if (isL) {
            __stcs(reinterpret_cast<float2*>(orow + 2), make_float2(o.z, o.w));
        } else {  // isR, interior
            __stcs(reinterpret_cast<float2*>(orow), make_float2(o.x, o.y));
        }
    };

    if (ty != 0 && ty != TILES_Y - 1) {
        // ================= interior tiles (94%): pointer-incremented, guard-free
        const float* rp = base  + (size_t)(y0 - 2) * IMG_W + cbase;  // next row to load
        float*       wp = obase + (size_t)y0 * IMG_W + cbase;        // next row to store

        float4 hA, hB, hC;
        float4 n0, n1, n2;
        {
            float4 t0 = *reinterpret_cast<const float4*>(rp); rp += IMG_W;
            float4 t1 = *reinterpret_cast<const float4*>(rp); rp += IMG_W;
            n0 = *reinterpret_cast<const float4*>(rp); rp += IMG_W;
            n1 = *reinterpret_cast<const float4*>(rp); rp += IMG_W;
            n2 = *reinterpret_cast<const float4*>(rp); rp += IMG_W;
            hminrow(t0, hA);
            hminrow(t1, hB);
        }
        float4 gA = make_float4(NINF, NINF, NINF, NINF);
        float4 gB = gA;

        #pragma unroll 6
        for (int i = 0; i < TH + 2; ++i) {
            const float4 cx = n0;
            n0 = n1; n1 = n2;
            n2 = *reinterpret_cast<const float4*>(rp); rp += IMG_W;

            hminrow(cx, hC);

            float4 e;
            e.x = min3f(hA.x, hB.x, hC.x);
            e.y = min3f(hA.y, hB.y, hC.y);
            e.z = min3f(hA.z, hB.z, hC.z);
            e.w = min3f(hA.w, hB.w, hC.w);

            float4 g;
            hmaxrow(e, g);

            if (i >= 2) {
                float4 o;
                o.x = max3f(gA.x, gB.x, g.x);
                o.y = max3f(gA.y, gB.y, g.y);
                o.z = max3f(gA.z, gB.z, g.z);
                o.w = max3f(gA.w, gB.w, g.w);
                store_out(o, wp);
                wp += IMG_W;
            }

            hA = hB; hB = hC;
            gA = gB; gB = g;
        }
    } else {
        // ================= image top/bottom tiles: clamped rows + g guard
        auto loadrow = [&](int r, float4& v) {
            int rc = min(max(r, 0), IMG_H - 1);
            v = *reinterpret_cast<const float4*>(base + (size_t)rc * IMG_W + cbase);
        };

        float4 hA, hB, hC;
        float4 n0, n1, n2;
        {
            float4 t0, t1;
            loadrow(y0 - 2, t0);
            loadrow(y0 - 1, t1);
            loadrow(y0,     n0);
            loadrow(y0 + 1, n1);
            loadrow(y0 + 2, n2);
            hminrow(t0, hA);
            hminrow(t1, hB);
        }
        float4 gA = make_float4(NINF, NINF, NINF, NINF);
        float4 gB = gA;

        #pragma unroll 6
        for (int r = y0 - 1; r <= y0 + TH; ++r) {
            const float4 cx = n0;
            n0 = n1; n1 = n2;
            loadrow(r + 4, n2);

            hminrow(cx, hC);

            float4 e;
            e.x = min3f(hA.x, hB.x, hC.x);
            e.y = min3f(hA.y, hB.y, hC.y);
            e.z = min3f(hA.z, hB.z, hC.z);
            e.w = min3f(hA.w, hB.w, hC.w);

            float4 g;
            if ((unsigned)r < (unsigned)IMG_H) {
                hmaxrow(e, g);
            } else {
                g = make_float4(NINF, NINF, NINF, NINF);
            }

            if (r - 1 >= y0) {
                float4 o;
                o.x = max3f(gA.x, gB.x, g.x);
                o.y = max3f(gA.y, gB.y, g.y);
                o.z = max3f(gA.z, gB.z, g.z);
                o.w = max3f(gA.w, gB.w, g.w);
                store_out(o, obase + (size_t)(r - 1) * IMG_W + cbase);
            }

            hA = hB; hB = hC;
            gA = gB; gB = g;
        }
    }
}

extern "C" void kernel_launch(void* const* d_in, const int* in_sizes, int n_in,
                              void* d_out, int out_size) {
    const float* x = (const float*)d_in[0];
    float* o = (float*)d_out;
    // 48 planes * 32 y-tiles * 9 x-tiles = 13824 warps; 64-thread blocks (2 warps)
    const int total_warps = PLANES * TILES_Y * TILES_X;
    const int blocks = (total_warps * 32 + 63) / 64;   // 6912
    morph_open_kernel<<<blocks, 64>>>(x, o);
}

// round 12
// speedup vs baseline: 1.0571x; 1.0571x over previous
#include <cuda_runtime.h>
#include <math_constants.h>

// Morphological opening: dilate3x3(erode3x3(x)), flat SE, geodesic SAME padding.
// x: (16,3,1024,1024) f32 -> 48 planes of 1024x1024.
//
// R7 converged design, one delta: plain write-back stores (no __stcs).
//   - warp loads 128 cols (lane l holds cols 4l..4l+3 as float4), owns 124 valid
//     output cols; tiles stride by 124 (9 x-tiles, last anchored at 896)
//   - horizontal min3/max3 purely via warp shuffles; interior edge lanes compute
//     2 garbage cols that are masked at store; at true image edges the +-inf
//     shuffle fill-ins are the exact geodesic pad
//   - vertical pad via CLAMP-TO-EDGE row replication (identity for min/max pad):
//     every row load is an unconditional LDG; the dilation-side -inf pad applies
//     to the intermediate, so the g=-inf check at r==-1 / r==1024 remains
//   - 3-deep register rings, 3-deep row prefetch, unroll 6 = lcm(3,2)
//   - plain stores: LTS holds the lines so the mid-sector tile-boundary writes
//     (496B stride => every boundary splits a 32B sector between two warps)
//     merge in L2 instead of evicting partial sectors to DRAM (RMW avoidance)
//   - TH=32 -> 6912 blocks of 64 thr at 16 blk/SM = 2.92 waves (tail ~3%)

#define TH      32
#define IMG_W   1024
#define IMG_H   1024
#define PLANES  48
#define TILES_X 9
#define TILE_STRIDE 124
#define TILES_Y (IMG_H / TH)    // 32

__device__ __forceinline__ float min3f(float a, float b, float c) {
    return fminf(a, fminf(b, c));
}
__device__ __forceinline__ float max3f(float a, float b, float c) {
    return fmaxf(a, fmaxf(b, c));
}

__global__ void __launch_bounds__(64, 16)
morph_open_kernel(const float* __restrict__ in, float* __restrict__ out) {
    const unsigned FULL = 0xffffffffu;
    const float INF  = CUDART_INF_F;
    const float NINF = -CUDART_INF_F;

    const int warp_g = blockIdx.x * 2 + (threadIdx.x >> 5);
    const int lane   = threadIdx.x & 31;

    const int tx = warp_g % TILES_X;
    const int ty = (warp_g / TILES_X) % TILES_Y;
    const int p  = warp_g / (TILES_X * TILES_Y);
    if (p >= PLANES) return;

    const float* __restrict__ base  = in  + (size_t)p * (IMG_W * IMG_H);
    float*       __restrict__ obase = out + (size_t)p * (IMG_W * IMG_H);

    // tile anchors: 0,124,...,868, then 896 (last tile right-aligned)
    const int x0 = (tx == TILES_X - 1) ? (IMG_W - 128) : tx * TILE_STRIDE;
    const int y0 = ty * TH;
    const int cbase = x0 + 4 * lane;
    const bool leftEdge  = (tx == 0);
    const bool rightEdge = (tx == TILES_X - 1);
    const bool isL = (lane == 0);
    const bool isR = (lane == 31);
    // lanes 1..30 always store float4; lane0 stores full only at image left edge,
    // lane31 full only at image right edge; otherwise masked float2.
    const bool storeFull = (!isL || leftEdge) && (!isR || rightEdge);

    // ---- row loader: UNCONDITIONAL, clamp-to-edge (identity for min/max pad)
    auto loadrow = [&](int r, float4& x4) {
        int rc = min(max(r, 0), IMG_H - 1);
        x4 = *reinterpret_cast<const float4*>(base + (size_t)rc * IMG_W + cbase);
    };

    // ---- horizontal min3 of one input row (shuffle-only)
    auto hminrow = [&](const float4& x, float4& h) {
        float xl = __shfl_up_sync(FULL, x.w, 1);
        if (isL) xl = INF;
        float xr = __shfl_down_sync(FULL, x.x, 1);
        if (isR) xr = INF;
        h.x = min3f(xl,  x.x, x.y);
        h.y = min3f(x.x, x.y, x.z);
        h.z = min3f(x.y, x.z, x.w);
        h.w = min3f(x.z, x.w, xr);
    };

    // ---- prologue: front-batch 5 row loads, then hmin rows y0-2, y0-1
    float4 hA, hB, hC;
    float4 t0, t1, n0x, n1x, n2x;
    loadrow(y0 - 2, t0);
    loadrow(y0 - 1, t1);
    loadrow(y0,     n0x);
    loadrow(y0 + 1, n1x);
    loadrow(y0 + 2, n2x);
    hminrow(t0, hA);
    hminrow(t1, hB);

    float4 gA = make_float4(NINF, NINF, NINF, NINF);
    float4 gB = gA;

    #pragma unroll 6
    for (int r = y0 - 1; r <= y0 + TH; ++r) {
        // consume prefetched row r+1; slide pipeline; prefetch row r+4 (clamped)
        const float4 cx = n0x;
        n0x = n1x; n1x = n2x;
        loadrow(r + 4, n2x);

        // hmin of row r+1
        hminrow(cx, hC);

        // erosion row r: vertical min of h(r-1),h(r),h(r+1)
        float4 e;
        e.x = min3f(hA.x, hB.x, hC.x);
        e.y = min3f(hA.y, hB.y, hC.y);
        e.z = min3f(hA.z, hB.z, hC.z);
        e.w = min3f(hA.w, hB.w, hC.w);

        // horizontal max3 of erosion row r -> g(r); rows outside image -> -inf
        // (the -inf pad applies to the INTERMEDIATE, so clamping can't replace it)
        float4 g;
        float el = __shfl_up_sync(FULL, e.w, 1);
        float er = __shfl_down_sync(FULL, e.x, 1);
        if (isL) el = NINF;
        if (isR) er = NINF;
        if ((unsigned)r < (unsigned)IMG_H) {
            g.x = max3f(el,  e.x, e.y);
            g.y = max3f(e.x, e.y, e.z);
            g.z = max3f(e.y, e.z, e.w);
            g.w = max3f(e.z, e.w, er);
        } else {
            g = make_float4(NINF, NINF, NINF, NINF);
        }

        // output row r-1: vertical max of g(r-2),g(r-1),g(r)
        if (r - 1 >= y0) {
            float4 o;
            o.x = max3f(gA.x, gB.x, g.x);
            o.y = max3f(gA.y, gB.y, g.y);
            o.z = max3f(gA.z, gB.z, g.z);
            o.w = max3f(gA.w, gB.w, g.w);
            float* orow = obase + (size_t)(r - 1) * IMG_W + cbase;
            if (storeFull) {
                *reinterpret_cast<float4*>(orow) = o;
            } else if (isL) {
                *reinterpret_cast<float2*>(orow + 2) = make_float2(o.z, o.w);
            } else { // isR, interior
                *reinterpret_cast<float2*>(orow) = make_float2(o.x, o.y);
            }
        }

        // rotate rings (renamed away by unroll-6: lcm(3,2))
        hA = hB; hB = hC;
        gA = gB; gB = g;
    }
}

extern "C" void kernel_launch(void* const* d_in, const int* in_sizes, int n_in,
                              void* d_out, int out_size) {
    const float* x = (const float*)d_in[0];
    float* o = (float*)d_out;
    // 48 planes * 32 y-tiles * 9 x-tiles = 13824 warps; 64-thread blocks (2 warps)
    const int total_warps = PLANES * TILES_Y * TILES_X;
    const int blocks = (total_warps * 32 + 63) / 64;   // 6912
    morph_open_kernel<<<blocks, 64>>>(x, o);
}

// round 13
// speedup vs baseline: 1.0817x; 1.0233x over previous
#include <cuda_runtime.h>
#include <math_constants.h>

// Morphological opening: dilate3x3(erode3x3(x)), flat SE, geodesic SAME padding.
// x: (16,3,1024,1024) f32 -> 48 planes of 1024x1024.
//
// CONVERGED FINAL (R7 configuration — measured best of 12 variants):
//   - fully fused single pass: one read + one write, DRAM traffic at the
//     402 MB floor, sustained ~5.9 TB/s (~75% of spec = practical mixed-stream
//     ceiling; issue/occupancy/MLP levers all falsified by A/B rounds)
//   - warp loads 128 cols (lane l holds cols 4l..4l+3 as float4), owns 124
//     valid output cols; tiles stride by 124 (9 x-tiles, last anchored at 896)
//   - horizontal min3/max3 purely via warp shuffles; interior edge lanes
//     compute 2 garbage cols masked at store (neighbor tile owns them);
//     at true image edges the +-inf shuffle fill-ins are the exact geodesic pad
//   - vertical pad via CLAMP-TO-EDGE row replication (identity for min/max
//     windows: min(x0,x0,x1)=min(x0,x1)) -> every row load is an UNCONDITIONAL
//     LDG; the dilation-side -inf pad applies to the intermediate, so the
//     g=-inf check at r==-1 / r==1024 remains (fires only on top/bottom tiles)
//   - 3-deep vertical register rings, 3-deep row prefetch, 5 front-batched
//     prologue loads, unroll 6 = lcm(3-ring, 2-ring) -> rotations become renames
//   - TH=32 -> 6912 blocks of 64 thr at 16 blk/SM = 2.92 waves (tail ~3%)
//   - 61 regs, zero smem, zero barriers, zero spills

#define TH      32
#define IMG_W   1024
#define IMG_H   1024
#define PLANES  48
#define TILES_X 9
#define TILE_STRIDE 124
#define TILES_Y (IMG_H / TH)    // 32

__device__ __forceinline__ float min3f(float a, float b, float c) {
    return fminf(a, fminf(b, c));
}
__device__ __forceinline__ float max3f(float a, float b, float c) {
    return fmaxf(a, fmaxf(b, c));
}

__global__ void __launch_bounds__(64, 16)
morph_open_kernel(const float* __restrict__ in, float* __restrict__ out) {
    const unsigned FULL = 0xffffffffu;
    const float INF  = CUDART_INF_F;
    const float NINF = -CUDART_INF_F;

    const int warp_g = blockIdx.x * 2 + (threadIdx.x >> 5);
    const int lane   = threadIdx.x & 31;

    const int tx = warp_g % TILES_X;
    const int ty = (warp_g / TILES_X) % TILES_Y;
    const int p  = warp_g / (TILES_X * TILES_Y);
    if (p >= PLANES) return;

    const float* __restrict__ base  = in  + (size_t)p * (IMG_W * IMG_H);
    float*       __restrict__ obase = out + (size_t)p * (IMG_W * IMG_H);

    // tile anchors: 0,124,...,868, then 896 (last tile right-aligned)
    const int x0 = (tx == TILES_X - 1) ? (IMG_W - 128) : tx * TILE_STRIDE;
    const int y0 = ty * TH;
    const int cbase = x0 + 4 * lane;
    const bool leftEdge  = (tx == 0);
    const bool rightEdge = (tx == TILES_X - 1);
    const bool isL = (lane == 0);
    const bool isR = (lane == 31);
    // lanes 1..30 always store float4; lane0 stores full only at image left edge,
    // lane31 full only at image right edge; otherwise masked float2.
    const bool storeFull = (!isL || leftEdge) && (!isR || rightEdge);

    // ---- row loader: UNCONDITIONAL, clamp-to-edge (identity for min/max pad)
    auto loadrow = [&](int r, float4& x4) {
        int rc = min(max(r, 0), IMG_H - 1);
        x4 = *reinterpret_cast<const float4*>(base + (size_t)rc * IMG_W + cbase);
    };

    // ---- horizontal min3 of one input row (shuffle-only)
    auto hminrow = [&](const float4& x, float4& h) {
        float xl = __shfl_up_sync(FULL, x.w, 1);
        if (isL) xl = INF;
        float xr = __shfl_down_sync(FULL, x.x, 1);
        if (isR) xr = INF;
        h.x = min3f(xl,  x.x, x.y);
        h.y = min3f(x.x, x.y, x.z);
        h.z = min3f(x.y, x.z, x.w);
        h.w = min3f(x.z, x.w, xr);
    };

    // ---- prologue: front-batch 5 row loads, then hmin rows y0-2, y0-1
    float4 hA, hB, hC;
    float4 t0, t1, n0x, n1x, n2x;
    loadrow(y0 - 2, t0);
    loadrow(y0 - 1, t1);
    loadrow(y0,     n0x);
    loadrow(y0 + 1, n1x);
    loadrow(y0 + 2, n2x);
    hminrow(t0, hA);
    hminrow(t1, hB);

    float4 gA = make_float4(NINF, NINF, NINF, NINF);
    float4 gB = gA;

    #pragma unroll 6
    for (int r = y0 - 1; r <= y0 + TH; ++r) {
        // consume prefetched row r+1; slide pipeline; prefetch row r+4 (clamped)
        const float4 cx = n0x;
        n0x = n1x; n1x = n2x;
        loadrow(r + 4, n2x);

        // hmin of row r+1
        hminrow(cx, hC);

        // erosion row r: vertical min of h(r-1),h(r),h(r+1)
        float4 e;
        e.x = min3f(hA.x, hB.x, hC.x);
        e.y = min3f(hA.y, hB.y, hC.y);
        e.z = min3f(hA.z, hB.z, hC.z);
        e.w = min3f(hA.w, hB.w, hC.w);

        // horizontal max3 of erosion row r -> g(r); rows outside image -> -inf
        // (the -inf pad applies to the INTERMEDIATE, so clamping can't replace it)
        float4 g;
        float el = __shfl_up_sync(FULL, e.w, 1);
        float er = __shfl_down_sync(FULL, e.x, 1);
        if (isL) el = NINF;
        if (isR) er = NINF;
        if ((unsigned)r < (unsigned)IMG_H) {
            g.x = max3f(el,  e.x, e.y);
            g.y = max3f(e.x, e.y, e.z);
            g.z = max3f(e.y, e.z, e.w);
            g.w = max3f(e.z, e.w, er);
        } else {
            g = make_float4(NINF, NINF, NINF, NINF);
        }

        // output row r-1: vertical max of g(r-2),g(r-1),g(r)
        if (r - 1 >= y0) {
            float4 o;
            o.x = max3f(gA.x, gB.x, g.x);
            o.y = max3f(gA.y, gB.y, g.y);
            o.z = max3f(gA.z, gB.z, g.z);
            o.w = max3f(gA.w, gB.w, g.w);
            float* orow = obase + (size_t)(r - 1) * IMG_W + cbase;
            if (storeFull) {
                __stcs(reinterpret_cast<float4*>(orow), o);
            } else if (isL) {
                __stcs(reinterpret_cast<float2*>(orow + 2), make_float2(o.z, o.w));
            } else { // isR, interior
                __stcs(reinterpret_cast<float2*>(orow), make_float2(o.x, o.y));
            }
        }

        // rotate rings (renamed away by unroll-6: lcm(3,2))
        hA = hB; hB = hC;
        gA = gB; gB = g;
    }
}

extern "C" void kernel_launch(void* const* d_in, const int* in_sizes, int n_in,
                              void* d_out, int out_size) {
    const float* x = (const float*)d_in[0];
    float* o = (float*)d_out;
    // 48 planes * 32 y-tiles * 9 x-tiles = 13824 warps; 64-thread blocks (2 warps)
    const int total_warps = PLANES * TILES_Y * TILES_X;
    const int blocks = (total_warps * 32 + 63) / 64;   // 6912
    morph_open_kernel<<<blocks, 64>>>(x, o);
}